// round 13
// baseline (speedup 1.0000x reference)
#include <cuda_runtime.h>
#include <cstdint>

// ---------------------------------------------------------------------------
// Noise2Void masked-MSE, exact replication of the JAX reference with
// jax.random.key(42) under the PARTITIONABLE threefry scheme (JAX >= 0.5
// default: jax_threefry_partitionable=True).
//
// Loss collapses to hot pixels only:
//   loss = sum_t (x[n,c,ry,rx] - x[n,c,hy,hx])^2 / (N*C*K)
//
// Fully integer reduction pipeline:
//   per-thread: q = round(d^2 * 2^18)            (u32, RN -> zero-mean error)
//   per-warp:   redux.sync.add.u32               (single instruction)
//   per-block:  integer add of 4 warp sums
//   global:     one packed u64 atomic  g_acc += (1<<54) | block_sum
// Integer adds are associative -> bitwise-deterministic independent of block
// arrival order. The block seeing prev>>54 == NBLK-1 holds the total
// in-register, writes out[0], resets g_acc (graph-replay idempotent).
//
// Overflow audit: |d|<=11 -> d^2<=121<2^7; item <= 2^25; warp sum < 2^30;
// global sum ~ 2^34 << 2^54 (count field at bit 54, max 192).
// ---------------------------------------------------------------------------

#define N_  32
#define C_  3
#define H_  512
#define W_  512
#define ITEMS 24576       // N_*C_*256
#define TPB  128
#define NBLK 192          // ITEMS / TPB

#define CNT_SHIFT 54
#define SUM_MASK  ((1ULL << CNT_SHIFT) - 1ULL)
#define FIX_SCALE 262144.0f   // 2^18

__device__ unsigned long long g_acc = 0ULL;

__host__ __device__ __forceinline__ uint32_t rotl32(uint32_t v, int r)
{
#ifdef __CUDA_ARCH__
    return __funnelshift_l(v, v, r);
#else
    return (v << r) | (v >> (32 - r));
#endif
}

__host__ __device__ __forceinline__ void threefry2x32(
    uint32_t k0, uint32_t k1, uint32_t x0, uint32_t x1,
    uint32_t &o0, uint32_t &o1)
{
    const uint32_t ks0 = k0, ks1 = k1, ks2 = k0 ^ k1 ^ 0x1BD11BDAu;
    x0 += ks0; x1 += ks1;
#define TF_R4(a,b,c,d)                                   \
    x0 += x1; x1 = rotl32(x1,(a)); x1 ^= x0;             \
    x0 += x1; x1 = rotl32(x1,(b)); x1 ^= x0;             \
    x0 += x1; x1 = rotl32(x1,(c)); x1 ^= x0;             \
    x0 += x1; x1 = rotl32(x1,(d)); x1 ^= x0;
    TF_R4(13,15,26, 6)  x0 += ks1; x1 += ks2 + 1u;
    TF_R4(17,29,16,24)  x0 += ks2; x1 += ks0 + 2u;
    TF_R4(13,15,26, 6)  x0 += ks0; x1 += ks1 + 3u;
    TF_R4(17,29,16,24)  x0 += ks1; x1 += ks2 + 4u;
    TF_R4(13,15,26, 6)  x0 += ks2; x1 += ks0 + 5u;
#undef TF_R4
    o0 = x0; o1 = x1;
}

// partitionable random_bits: 32-bit element i = o0 ^ o1 of block (0, i)
__device__ __forceinline__ uint32_t rb32(uint32_t k0, uint32_t k1, uint32_t i)
{
    uint32_t o0, o1;
    threefry2x32(k0, k1, 0u, i, o0, o1);
    return o0 ^ o1;
}

__global__ void __launch_bounds__(TPB)
n2v_fused(const float* __restrict__ x, float* __restrict__ out,
          uint32_t kl0, uint32_t kl1,   // randint lower-bits key
          uint32_t ku0, uint32_t ku1)   // uniform key (k2)
{
    const int tid  = threadIdx.x;
    const int lane = tid & 31;
    const int wid  = tid >> 5;
    const int t    = blockIdx.x * TPB + tid;   // item index in [0, ITEMS)

    // --- Phase 1: offset RNG (y, x) -> hot pixel; issue its load early ---
    uint32_t oy = rb32(kl0, kl1, (uint32_t)(2 * t));
    uint32_t ox = rb32(kl0, kl1, (uint32_t)(2 * t + 1));

    int nc = t >> 8;            // n*C + c
    int k  = t & 255;
    int by = k >> 4;
    int bx = k & 15;

    int hy = by * 32 + (int)(oy & 31u);
    int hx = bx * 32 + (int)(ox & 31u);

    const float* img = x + (size_t)nc * (H_ * W_);
    float b = __ldg(img + hy * W_ + hx);      // long-scoreboard hidden below

    // ROI bounds (independent of the uniform draw), faithful quirk:
    // roimax = min(hc+3, shape-1)  ->  sh in {2,3,4,5} (2 at coord 511)
    int rmin0 = max(hy - 2, 0);
    int rmax0 = min(hy + 3, H_ - 1);
    int rmin1 = max(hx - 2, 0);
    int rmax1 = min(hx + 3, W_ - 1);
    int sh0 = rmax0 - rmin0;
    int sh1 = rmax1 - rmin1;           // in {2,3,4,5}

    bool hasc = (sh0 > 2) && (sh1 > 2);
    int m = sh0 * sh1 - (hasc ? 1 : 0);

    // --- Phase 2: uniform RNG -> replacement pixel ---
    uint32_t ub = rb32(ku0, ku1, (uint32_t)t);

    // uniform in [0,1): bitcast((bits>>9)|0x3f800000) - 1.0
    float uf = __uint_as_float((ub >> 9) | 0x3f800000u) - 1.0f;
    int u = __float2int_rd(uf * (float)m);   // floor, u in [0, m-1]
    u = min(u, m - 1);
    int cflat = 2 * sh1 + 2;                 // flat index of rc=(2,2)
    if (hasc && u >= cflat) u += 1;

    // u / sh1, u % sh1 via exact reciprocal (sh1 in {2,3,4,5}, u <= 24):
    // 0.5 and 0.25 exact; 1/3 and 1/5 RN round UP -> truncation exact for
    // all u <= 24 (exact multiples round back to the integer; non-multiples
    // stay >= 0.2 below the next integer).
    float rcp = (sh1 <= 3) ? ((sh1 == 2) ? 0.5f
                                         : __uint_as_float(0x3EAAAAABu))  // 1/3
              : ((sh1 == 4) ? 0.25f
                            : __uint_as_float(0x3E4CCCCDu));              // 1/5
    int q = __float2int_rz((float)u * rcp);
    int r = u - q * sh1;

    int ry = rmin0 + q;
    int rx = rmin1 + r;

    float a = __ldg(img + ry * W_ + rx);
    float d = a - b;

    // ---- per-thread fixed-point convert (RN: zero-mean quantization) ----
    uint32_t qv = __float2uint_rn(d * d * FIX_SCALE);

    // ---- warp reduction: single redux.sync.add.u32 ----
    uint32_t wsumv = __reduce_add_sync(0xFFFFFFFFu, qv);

    __shared__ uint32_t wsum[TPB / 32];
    if (lane == 0) wsum[wid] = wsumv;
    __syncthreads();

    if (tid == 0) {
        unsigned long long contrib =
            (unsigned long long)((wsum[0] + wsum[1]) + (wsum[2] + wsum[3]));
        unsigned long long prev =
            atomicAdd(&g_acc, (1ULL << CNT_SHIFT) + contrib);

        if ((prev >> CNT_SHIFT) == (unsigned long long)(NBLK - 1)) {
            // all other blocks' atomics have completed; total is in-register
            unsigned long long total = ((prev & SUM_MASK) + contrib) & SUM_MASK;
            g_acc = 0ULL;  // reset for next graph replay (race-free: we're last)
            // scale = 2^-18 (undo fixed point) / 24576 (mask.sum())
            out[0] = (float)total * (1.0f / (FIX_SCALE * 24576.0f));
        }
    }
}

extern "C" void kernel_launch(void* const* d_in, const int* in_sizes, int n_in,
                              void* d_out, int out_size)
{
    (void)in_sizes; (void)n_in; (void)out_size;
    const float* x = (const float*)d_in[0];
    float* out = (float*)d_out;

    // ---- Derive JAX keys on host (pure CPU math, graph-capture safe) ----
    // root = key(42) = (0, 42)
    uint32_t A0, A1, B0, B1;
    // split(root, 2) foldlike: sub-key i = full block threefry(root; 0, i)
    threefry2x32(0u, 42u, 0u, 0u, A0, A1);   // k1 (randint key)
    threefry2x32(0u, 42u, 0u, 1u, B0, B1);   // k2 (uniform key)

    // randint internally splits k1 (foldlike); lower_bits uses the SECOND
    // sub-key = threefry(k1; 0, 1). (higher-bits key unused: (2^16 % 32)^2 % 32 = 0)
    uint32_t kl0, kl1;
    threefry2x32(A0, A1, 0u, 1u, kl0, kl1);

    n2v_fused<<<NBLK, TPB>>>(x, out, kl0, kl1, B0, B1);
}

// round 14
// speedup vs baseline: 1.0048x; 1.0048x over previous
#include <cuda_runtime.h>
#include <cstdint>

// ---------------------------------------------------------------------------
// Noise2Void masked-MSE, exact replication of the JAX reference with
// jax.random.key(42) under the PARTITIONABLE threefry scheme (JAX >= 0.5
// default: jax_threefry_partitionable=True).
//
// Loss collapses to hot pixels only:
//   loss = sum_t (x[n,c,ry,rx] - x[n,c,hy,hx])^2 / (N*C*K)
//
// Single-warp blocks (TPB=32): the whole block reduction is ONE
// redux.sync.add.u32; lane 0 fires one packed u64 atomic:
//   g_acc += (1 << 54) | warp_sum          (warp_sum = sum round(d^2 * 2^18))
// No __syncthreads, no shared memory anywhere. Integer adds are associative
// -> bitwise-deterministic independent of block arrival order. The block
// seeing prev>>54 == NBLK-1 holds the total in-register, writes out[0],
// resets g_acc (graph-replay idempotent).
//
// Overflow audit: |d|<=11 -> d^2*2^18 <= 2^25; warp sum < 2^30; global sum
// ~ 2^34 << 2^54 (count field at bit 54, max 768 < 2^10).
// ---------------------------------------------------------------------------

#define N_  32
#define C_  3
#define H_  512
#define W_  512
#define ITEMS 24576       // N_*C_*256
#define TPB  32
#define NBLK 768          // ITEMS / TPB

#define CNT_SHIFT 54
#define SUM_MASK  ((1ULL << CNT_SHIFT) - 1ULL)
#define FIX_SCALE 262144.0f   // 2^18

__device__ unsigned long long g_acc = 0ULL;

__host__ __device__ __forceinline__ uint32_t rotl32(uint32_t v, int r)
{
#ifdef __CUDA_ARCH__
    return __funnelshift_l(v, v, r);
#else
    return (v << r) | (v >> (32 - r));
#endif
}

__host__ __device__ __forceinline__ void threefry2x32(
    uint32_t k0, uint32_t k1, uint32_t x0, uint32_t x1,
    uint32_t &o0, uint32_t &o1)
{
    const uint32_t ks0 = k0, ks1 = k1, ks2 = k0 ^ k1 ^ 0x1BD11BDAu;
    x0 += ks0; x1 += ks1;
#define TF_R4(a,b,c,d)                                   \
    x0 += x1; x1 = rotl32(x1,(a)); x1 ^= x0;             \
    x0 += x1; x1 = rotl32(x1,(b)); x1 ^= x0;             \
    x0 += x1; x1 = rotl32(x1,(c)); x1 ^= x0;             \
    x0 += x1; x1 = rotl32(x1,(d)); x1 ^= x0;
    TF_R4(13,15,26, 6)  x0 += ks1; x1 += ks2 + 1u;
    TF_R4(17,29,16,24)  x0 += ks2; x1 += ks0 + 2u;
    TF_R4(13,15,26, 6)  x0 += ks0; x1 += ks1 + 3u;
    TF_R4(17,29,16,24)  x0 += ks1; x1 += ks2 + 4u;
    TF_R4(13,15,26, 6)  x0 += ks2; x1 += ks0 + 5u;
#undef TF_R4
    o0 = x0; o1 = x1;
}

// partitionable random_bits: 32-bit element i = o0 ^ o1 of block (0, i)
__device__ __forceinline__ uint32_t rb32(uint32_t k0, uint32_t k1, uint32_t i)
{
    uint32_t o0, o1;
    threefry2x32(k0, k1, 0u, i, o0, o1);
    return o0 ^ o1;
}

__global__ void __launch_bounds__(TPB)
n2v_fused(const float* __restrict__ x, float* __restrict__ out,
          uint32_t kl0, uint32_t kl1,   // randint lower-bits key
          uint32_t ku0, uint32_t ku1)   // uniform key (k2)
{
    const int lane = threadIdx.x;                 // TPB == 32
    const int t    = blockIdx.x * TPB + lane;     // item index in [0, ITEMS)

    // --- Phase 1: offset RNG (y, x) -> hot pixel; issue its load early ---
    uint32_t oy = rb32(kl0, kl1, (uint32_t)(2 * t));
    uint32_t ox = rb32(kl0, kl1, (uint32_t)(2 * t + 1));

    int nc = t >> 8;            // n*C + c
    int k  = t & 255;
    int by = k >> 4;
    int bx = k & 15;

    int hy = by * 32 + (int)(oy & 31u);
    int hx = bx * 32 + (int)(ox & 31u);

    const float* img = x + (size_t)nc * (H_ * W_);
    float b = __ldg(img + hy * W_ + hx);      // long-scoreboard hidden below

    // ROI bounds (independent of the uniform draw), faithful quirk:
    // roimax = min(hc+3, shape-1)  ->  sh in {2,3,4,5} (2 at coord 511)
    int rmin0 = max(hy - 2, 0);
    int rmax0 = min(hy + 3, H_ - 1);
    int rmin1 = max(hx - 2, 0);
    int rmax1 = min(hx + 3, W_ - 1);
    int sh0 = rmax0 - rmin0;
    int sh1 = rmax1 - rmin1;           // in {2,3,4,5}

    bool hasc = (sh0 > 2) && (sh1 > 2);
    int m = sh0 * sh1 - (hasc ? 1 : 0);

    // --- Phase 2: uniform RNG -> replacement pixel ---
    uint32_t ub = rb32(ku0, ku1, (uint32_t)t);

    // uniform in [0,1): bitcast((bits>>9)|0x3f800000) - 1.0
    float uf = __uint_as_float((ub >> 9) | 0x3f800000u) - 1.0f;
    int u = __float2int_rd(uf * (float)m);   // floor, u in [0, m-1]
    u = min(u, m - 1);
    int cflat = 2 * sh1 + 2;                 // flat index of rc=(2,2)
    if (hasc && u >= cflat) u += 1;

    // u / sh1, u % sh1 via exact reciprocal (sh1 in {2,3,4,5}, u <= 24):
    // 0.5 and 0.25 exact; 1/3 and 1/5 RN round UP -> truncation exact for
    // all u <= 24 (exact multiples round back to the integer; non-multiples
    // stay >= 0.2 below the next integer).
    float rcp = (sh1 <= 3) ? ((sh1 == 2) ? 0.5f
                                         : __uint_as_float(0x3EAAAAABu))  // 1/3
              : ((sh1 == 4) ? 0.25f
                            : __uint_as_float(0x3E4CCCCDu));              // 1/5
    int q = __float2int_rz((float)u * rcp);
    int r = u - q * sh1;

    int ry = rmin0 + q;
    int rx = rmin1 + r;

    float a = __ldg(img + ry * W_ + rx);
    float d = a - b;

    // ---- per-thread fixed-point convert (RN: zero-mean quantization) ----
    uint32_t qv = __float2uint_rn(d * d * FIX_SCALE);

    // ---- whole-block reduction: single redux.sync.add.u32 ----
    uint32_t wsumv = __reduce_add_sync(0xFFFFFFFFu, qv);

    if (lane == 0) {
        unsigned long long contrib = (unsigned long long)wsumv;
        unsigned long long prev =
            atomicAdd(&g_acc, (1ULL << CNT_SHIFT) + contrib);

        if ((prev >> CNT_SHIFT) == (unsigned long long)(NBLK - 1)) {
            // all other blocks' atomics have completed; total is in-register
            unsigned long long total = ((prev & SUM_MASK) + contrib) & SUM_MASK;
            g_acc = 0ULL;  // reset for next graph replay (race-free: we're last)
            // scale = 2^-18 (undo fixed point) / 24576 (mask.sum())
            out[0] = (float)total * (1.0f / (FIX_SCALE * 24576.0f));
        }
    }
}

extern "C" void kernel_launch(void* const* d_in, const int* in_sizes, int n_in,
                              void* d_out, int out_size)
{
    (void)in_sizes; (void)n_in; (void)out_size;
    const float* x = (const float*)d_in[0];
    float* out = (float*)d_out;

    // ---- Derive JAX keys on host (pure CPU math, graph-capture safe) ----
    // root = key(42) = (0, 42)
    uint32_t A0, A1, B0, B1;
    // split(root, 2) foldlike: sub-key i = full block threefry(root; 0, i)
    threefry2x32(0u, 42u, 0u, 0u, A0, A1);   // k1 (randint key)
    threefry2x32(0u, 42u, 0u, 1u, B0, B1);   // k2 (uniform key)

    // randint internally splits k1 (foldlike); lower_bits uses the SECOND
    // sub-key = threefry(k1; 0, 1). (higher-bits key unused: (2^16 % 32)^2 % 32 = 0)
    uint32_t kl0, kl1;
    threefry2x32(A0, A1, 0u, 1u, kl0, kl1);

    n2v_fused<<<NBLK, TPB>>>(x, out, kl0, kl1, B0, B1);
}

// round 15
// speedup vs baseline: 1.0097x; 1.0048x over previous
#include <cuda_runtime.h>
#include <cstdint>

// ---------------------------------------------------------------------------
// Noise2Void masked-MSE, exact replication of the JAX reference with
// jax.random.key(42) under the PARTITIONABLE threefry scheme (JAX >= 0.5
// default: jax_threefry_partitionable=True).
//
// Loss collapses to hot pixels only:
//   loss = sum_t (x[n,c,ry,rx] - x[n,c,hy,hx])^2 / (N*C*K)
//
// Single-warp blocks (TPB=32): the whole block reduction is ONE
// redux.sync.add.u32; lane 0 fires one packed u64 atomic:
//   g_acc += (1 << 54) | warp_sum          (warp_sum = sum round(d^2 * 2^18))
// No __syncthreads, no shared memory anywhere. Integer adds are associative
// -> bitwise-deterministic independent of block arrival order. The block
// seeing prev>>54 == NBLK-1 holds the total in-register, writes out[0],
// resets g_acc (graph-replay idempotent).
//
// Overflow audit: |d|<=11 -> d^2*2^18 <= 2^25; warp sum < 2^30; global sum
// ~ 2^34 << 2^54 (count field at bit 54, max 768 < 2^10).
//
// CONVERGED: the RNG contract forces 3 threefry blocks per item (~200K
// warp-instrs chip-wide ~= 670 cyc/SMSP issue floor, arrangement-invariant),
// plus one unprefetchable scattered DRAM load (address depends on the
// uniform draw) and ~4us single-kernel launch/ramp floor. Remaining levers
// are all < 0.1us.
// ---------------------------------------------------------------------------

#define N_  32
#define C_  3
#define H_  512
#define W_  512
#define ITEMS 24576       // N_*C_*256
#define TPB  32
#define NBLK 768          // ITEMS / TPB

#define CNT_SHIFT 54
#define SUM_MASK  ((1ULL << CNT_SHIFT) - 1ULL)
#define FIX_SCALE 262144.0f   // 2^18

__device__ unsigned long long g_acc = 0ULL;

__host__ __device__ __forceinline__ uint32_t rotl32(uint32_t v, int r)
{
#ifdef __CUDA_ARCH__
    return __funnelshift_l(v, v, r);
#else
    return (v << r) | (v >> (32 - r));
#endif
}

__host__ __device__ __forceinline__ void threefry2x32(
    uint32_t k0, uint32_t k1, uint32_t x0, uint32_t x1,
    uint32_t &o0, uint32_t &o1)
{
    const uint32_t ks0 = k0, ks1 = k1, ks2 = k0 ^ k1 ^ 0x1BD11BDAu;
    x0 += ks0; x1 += ks1;
#define TF_R4(a,b,c,d)                                   \
    x0 += x1; x1 = rotl32(x1,(a)); x1 ^= x0;             \
    x0 += x1; x1 = rotl32(x1,(b)); x1 ^= x0;             \
    x0 += x1; x1 = rotl32(x1,(c)); x1 ^= x0;             \
    x0 += x1; x1 = rotl32(x1,(d)); x1 ^= x0;
    TF_R4(13,15,26, 6)  x0 += ks1; x1 += ks2 + 1u;
    TF_R4(17,29,16,24)  x0 += ks2; x1 += ks0 + 2u;
    TF_R4(13,15,26, 6)  x0 += ks0; x1 += ks1 + 3u;
    TF_R4(17,29,16,24)  x0 += ks1; x1 += ks2 + 4u;
    TF_R4(13,15,26, 6)  x0 += ks2; x1 += ks0 + 5u;
#undef TF_R4
    o0 = x0; o1 = x1;
}

// partitionable random_bits: 32-bit element i = o0 ^ o1 of block (0, i)
__device__ __forceinline__ uint32_t rb32(uint32_t k0, uint32_t k1, uint32_t i)
{
    uint32_t o0, o1;
    threefry2x32(k0, k1, 0u, i, o0, o1);
    return o0 ^ o1;
}

__global__ void __launch_bounds__(TPB)
n2v_fused(const float* __restrict__ x, float* __restrict__ out,
          uint32_t kl0, uint32_t kl1,   // randint lower-bits key
          uint32_t ku0, uint32_t ku1)   // uniform key (k2)
{
    const int lane = threadIdx.x;                 // TPB == 32
    const int t    = blockIdx.x * TPB + lane;     // item index in [0, ITEMS)

    // --- Phase 1: offset RNG (y, x) -> hot pixel; issue its load early ---
    uint32_t oy = rb32(kl0, kl1, (uint32_t)(2 * t));
    uint32_t ox = rb32(kl0, kl1, (uint32_t)(2 * t + 1));

    int nc = t >> 8;            // n*C + c
    int k  = t & 255;
    int by = k >> 4;
    int bx = k & 15;

    int hy = by * 32 + (int)(oy & 31u);
    int hx = bx * 32 + (int)(ox & 31u);

    const float* img = x + (size_t)nc * (H_ * W_);
    float b = __ldg(img + hy * W_ + hx);      // long-scoreboard hidden below

    // ROI bounds (independent of the uniform draw), faithful quirk:
    // roimax = min(hc+3, shape-1)  ->  sh in {2,3,4,5} (2 at coord 511)
    int rmin0 = max(hy - 2, 0);
    int rmax0 = min(hy + 3, H_ - 1);
    int rmin1 = max(hx - 2, 0);
    int rmax1 = min(hx + 3, W_ - 1);
    int sh0 = rmax0 - rmin0;
    int sh1 = rmax1 - rmin1;           // in {2,3,4,5}

    bool hasc = (sh0 > 2) && (sh1 > 2);
    int m = sh0 * sh1 - (hasc ? 1 : 0);

    // --- Phase 2: uniform RNG -> replacement pixel ---
    uint32_t ub = rb32(ku0, ku1, (uint32_t)t);

    // uniform in [0,1): bitcast((bits>>9)|0x3f800000) - 1.0
    float uf = __uint_as_float((ub >> 9) | 0x3f800000u) - 1.0f;
    int u = __float2int_rd(uf * (float)m);   // floor, u in [0, m-1]
    u = min(u, m - 1);
    int cflat = 2 * sh1 + 2;                 // flat index of rc=(2,2)
    if (hasc && u >= cflat) u += 1;

    // u / sh1, u % sh1 via exact reciprocal (sh1 in {2,3,4,5}, u <= 24):
    // 0.5 and 0.25 exact; 1/3 and 1/5 RN round UP -> truncation exact for
    // all u <= 24 (exact multiples round back to the integer; non-multiples
    // stay >= 0.2 below the next integer).
    float rcp = (sh1 <= 3) ? ((sh1 == 2) ? 0.5f
                                         : __uint_as_float(0x3EAAAAABu))  // 1/3
              : ((sh1 == 4) ? 0.25f
                            : __uint_as_float(0x3E4CCCCDu));              // 1/5
    int q = __float2int_rz((float)u * rcp);
    int r = u - q * sh1;

    int ry = rmin0 + q;
    int rx = rmin1 + r;

    float a = __ldg(img + ry * W_ + rx);
    float d = a - b;

    // ---- per-thread fixed-point convert (RN: zero-mean quantization) ----
    uint32_t qv = __float2uint_rn(d * d * FIX_SCALE);

    // ---- whole-block reduction: single redux.sync.add.u32 ----
    uint32_t wsumv = __reduce_add_sync(0xFFFFFFFFu, qv);

    if (lane == 0) {
        unsigned long long contrib = (unsigned long long)wsumv;
        unsigned long long prev =
            atomicAdd(&g_acc, (1ULL << CNT_SHIFT) + contrib);

        if ((prev >> CNT_SHIFT) == (unsigned long long)(NBLK - 1)) {
            // all other blocks' atomics have completed; total is in-register
            unsigned long long total = ((prev & SUM_MASK) + contrib) & SUM_MASK;
            g_acc = 0ULL;  // reset for next graph replay (race-free: we're last)
            // scale = 2^-18 (undo fixed point) / 24576 (mask.sum())
            out[0] = (float)total * (1.0f / (FIX_SCALE * 24576.0f));
        }
    }
}

extern "C" void kernel_launch(void* const* d_in, const int* in_sizes, int n_in,
                              void* d_out, int out_size)
{
    (void)in_sizes; (void)n_in; (void)out_size;
    const float* x = (const float*)d_in[0];
    float* out = (float*)d_out;

    // ---- Derive JAX keys on host (pure CPU math, graph-capture safe) ----
    // root = key(42) = (0, 42)
    uint32_t A0, A1, B0, B1;
    // split(root, 2) foldlike: sub-key i = full block threefry(root; 0, i)
    threefry2x32(0u, 42u, 0u, 0u, A0, A1);   // k1 (randint key)
    threefry2x32(0u, 42u, 0u, 1u, B0, B1);   // k2 (uniform key)

    // randint internally splits k1 (foldlike); lower_bits uses the SECOND
    // sub-key = threefry(k1; 0, 1). (higher-bits key unused: (2^16 % 32)^2 % 32 = 0)
    uint32_t kl0, kl1;
    threefry2x32(A0, A1, 0u, 1u, kl0, kl1);

    n2v_fused<<<NBLK, TPB>>>(x, out, kl0, kl1, B0, B1);
}